// round 5
// baseline (speedup 1.0000x reference)
#include <cuda_runtime.h>

// Analytic collapse of SpatialAttentionLayer:
// V = ones(B,L,O,d)  =>
//   relu(V@Wk+bk) = rk[d] = relu(colsum(Wk)+bk), constant over (b,l,o)
//   _attention_net(...) is constant along the softmax axis (i), so
//   phi = psi = theta = 1/O uniformly, and phi @ rk-rows = rk.
// => M[b,l,o,d] = r1[d]+r2[d]+r3[d]+r4[d], broadcast to [8,12,64,128].

#define D 128

__device__ float g_r[D];

__global__ void reduce_r_kernel(const float* __restrict__ W1, const float* __restrict__ b1,
                                const float* __restrict__ W2, const float* __restrict__ b2,
                                const float* __restrict__ W3, const float* __restrict__ b3,
                                const float* __restrict__ W4, const float* __restrict__ b4) {
    const int d = threadIdx.x;  // 0..127
    const float* Ws[4] = {W1, W2, W3, W4};
    const float* bs[4] = {b1, b2, b3, b4};
    float acc = 0.0f;
#pragma unroll
    for (int k = 0; k < 4; ++k) {
        const float* __restrict__ W = Ws[k];
        float s = bs[k][d];
#pragma unroll 16
        for (int i = 0; i < D; ++i) {
            s += W[i * D + d];      // coalesced across the 128 threads
        }
        acc += fmaxf(s, 0.0f);
    }
    g_r[d] = acc;
}

__global__ void broadcast_kernel(float4* __restrict__ out, int n4) {
    int i = blockIdx.x * blockDim.x + threadIdx.x;
    if (i < n4) {
        // blockDim is a multiple of 32, so (i & 31) == (threadIdx.x & 31):
        // each float4 covers 4 consecutive d; 32 float4 per 128-wide row.
        const float4* r4 = reinterpret_cast<const float4*>(g_r);
        out[i] = r4[threadIdx.x & 31];
    }
}

extern "C" void kernel_launch(void* const* d_in, const int* in_sizes, int n_in,
                              void* d_out, int out_size) {
    // metadata order: X(0), a{W1,b1,W2,b2,w3,b3}(1..6), b{...}(7..12),
    // c{...}(13..18), W1(19),b1(20),W2(21),b2(22),W3(23),b3(24),W4(25),b4(26)
    const float* W1 = (const float*)d_in[19];
    const float* b1 = (const float*)d_in[20];
    const float* W2 = (const float*)d_in[21];
    const float* b2 = (const float*)d_in[22];
    const float* W3 = (const float*)d_in[23];
    const float* b3 = (const float*)d_in[24];
    const float* W4 = (const float*)d_in[25];
    const float* b4 = (const float*)d_in[26];

    reduce_r_kernel<<<1, D>>>(W1, b1, W2, b2, W3, b3, W4, b4);

    int n4 = out_size / 4;  // 786432 / 4 = 196608 float4 stores
    int threads = 256;
    int blocks = (n4 + threads - 1) / threads;
    broadcast_kernel<<<blocks, threads>>>((float4*)d_out, n4);
}

// round 6
// speedup vs baseline: 1.7380x; 1.7380x over previous
#include <cuda_runtime.h>

// Analytic collapse of SpatialAttentionLayer:
// V = ones(B,L,O,d)  =>
//   relu(V@Wk+bk) = rk[d] = relu(colsum(Wk)[d] + bk[d]), constant over (b,l,o)
//   _attention_net rows constant along softmax axis => phi=psi=theta=1/O,
//   and (1/O ones) @ rk-rows = rk.
// => M[b,l,o,d] = r1[d]+r2[d]+r3[d]+r4[d], broadcast to [8,12,64,128].

#define D 128

// Per-matrix relu'd column sums: g_rk[k][d]
__device__ float g_rk[4][D];

// 4 blocks (one per weight matrix) x 1024 threads.
// thread (d = tid&127, q = tid>>7) sums rows [16q, 16q+16) of column d.
__global__ void __launch_bounds__(1024, 1)
reduce_r_kernel(const float* __restrict__ W1, const float* __restrict__ b1,
                const float* __restrict__ W2, const float* __restrict__ b2,
                const float* __restrict__ W3, const float* __restrict__ b3,
                const float* __restrict__ W4, const float* __restrict__ b4) {
    __shared__ float part[8][D];

    const int k = blockIdx.x;            // 0..3
    const int tid = threadIdx.x;
    const int d = tid & (D - 1);
    const int q = tid >> 7;              // 0..7

    const float* __restrict__ W = (k == 0) ? W1 : (k == 1) ? W2 : (k == 2) ? W3 : W4;
    const float* __restrict__ b = (k == 0) ? b1 : (k == 1) ? b2 : (k == 2) ? b3 : b4;

    const float* __restrict__ p = W + (q * 16) * D + d;
    float s = 0.0f;
#pragma unroll
    for (int i = 0; i < 16; ++i) {
        s += p[i * D];                   // coalesced across the 128 d-threads
    }
    part[q][d] = s;
    __syncthreads();

    if (tid < D) {
        float acc = b[tid];
#pragma unroll
        for (int qq = 0; qq < 8; ++qq) acc += part[qq][tid];
        g_rk[k][tid] = fmaxf(acc, 0.0f);
    }
}

// 256 blocks x 256 threads; each thread sums its quad from the 4 rk vectors
// once (registers), then writes 3 float4s. Strides are multiples of 32 so
// (i & 31) stays equal to (threadIdx.x & 31) across iterations.
__global__ void __launch_bounds__(256)
broadcast_kernel(float4* __restrict__ out, int n4) {
    const int quad = threadIdx.x & 31;
    const float4* __restrict__ r0 = reinterpret_cast<const float4*>(g_rk[0]);
    const float4* __restrict__ r1 = reinterpret_cast<const float4*>(g_rk[1]);
    const float4* __restrict__ r2 = reinterpret_cast<const float4*>(g_rk[2]);
    const float4* __restrict__ r3 = reinterpret_cast<const float4*>(g_rk[3]);

    float4 a = r0[quad], v1 = r1[quad], v2 = r2[quad], v3 = r3[quad];
    a.x += v1.x + v2.x + v3.x;
    a.y += v1.y + v2.y + v3.y;
    a.z += v1.z + v2.z + v3.z;
    a.w += v1.w + v2.w + v3.w;

    const int stride = gridDim.x * blockDim.x;         // 65536 (mult of 32)
    int i = blockIdx.x * blockDim.x + threadIdx.x;
#pragma unroll 3
    for (; i < n4; i += stride) {
        out[i] = a;
    }
}

extern "C" void kernel_launch(void* const* d_in, const int* in_sizes, int n_in,
                              void* d_out, int out_size) {
    // metadata order: X(0), a{W1,b1,W2,b2,w3,b3}(1..6), b{...}(7..12),
    // c{...}(13..18), W1(19),b1(20),W2(21),b2(22),W3(23),b3(24),W4(25),b4(26)
    const float* W1 = (const float*)d_in[19];
    const float* b1 = (const float*)d_in[20];
    const float* W2 = (const float*)d_in[21];
    const float* b2 = (const float*)d_in[22];
    const float* W3 = (const float*)d_in[23];
    const float* b3 = (const float*)d_in[24];
    const float* W4 = (const float*)d_in[25];
    const float* b4 = (const float*)d_in[26];

    reduce_r_kernel<<<4, 1024>>>(W1, b1, W2, b2, W3, b3, W4, b4);

    const int n4 = out_size / 4;  // 196608 float4 stores
    broadcast_kernel<<<256, 256>>>((float4*)d_out, n4);
}